// round 2
// baseline (speedup 1.0000x reference)
#include <cuda_runtime.h>

#define BB    16
#define CIN   512
#define COUT  512
#define RES   64
#define WDIM  512

// scratch (device globals — no allocations allowed)
__device__ float g_styles[BB * CIN];    // 32 KB
__device__ float g_wsqT[CIN * COUT];    // 1 MB, transposed: [cin][cout]
__device__ float g_dcoefs[BB * COUT];   // 32 KB

// ---------------------------------------------------------------------------
// Kernel 1: styles[b,cin] = m1*m2 + m3 from the affine projection
// grid = B, block = 512 (one thread per cin)
// ---------------------------------------------------------------------------
__global__ void k_styles(const float* __restrict__ w,
                         const float* __restrict__ affine_w,
                         const float* __restrict__ affine_b) {
    const int b = blockIdx.x;
    const int t = threadIdx.x;               // cin index
    __shared__ float sw[WDIM];
    sw[t] = w[b * WDIM + t];
    __syncthreads();

    const float gain = 1.0f / sqrtf((float)WDIM);
    float m[3];
#pragma unroll
    for (int j0 = 0; j0 < 3; j0++) {
        const int j = j0 * CIN + t;
        const float* __restrict__ row = affine_w + (size_t)j * WDIM;
        float acc = 0.f;
        for (int k = 0; k < WDIM; k++) acc += row[k] * sw[k];
        m[j0] = acc * gain + affine_b[j];
    }
    g_styles[b * CIN + t] = m[0] * m[1] + m[2];
}

// ---------------------------------------------------------------------------
// Kernel 2: wsqT[cin][cout] = sum_{kh,kw} weight[cout,cin,kh,kw]^2
// ---------------------------------------------------------------------------
__global__ void k_wsq(const float* __restrict__ weight) {
    const int id = blockIdx.x * blockDim.x + threadIdx.x;  // CIN*COUT threads
    const int cin  = id / COUT;
    const int cout = id - cin * COUT;
    const float* __restrict__ p = weight + ((size_t)cout * CIN + cin) * 9;
    float s = 0.f;
#pragma unroll
    for (int i = 0; i < 9; i++) { float v = p[i]; s += v * v; }
    g_wsqT[cin * COUT + cout] = s;
}

// ---------------------------------------------------------------------------
// Kernel 3: dcoefs[b,cout] = rsqrt( sum_cin styles^2 * wsqT + 1e-8 )
// grid = B, block = 512 (one thread per cout)
// ---------------------------------------------------------------------------
__global__ void k_dcoefs() {
    const int b = blockIdx.x;
    const int t = threadIdx.x;               // cout
    __shared__ float s2[CIN];
    const float st = g_styles[b * CIN + t];  // CIN == COUT == 512
    s2[t] = st * st;
    __syncthreads();
    float acc = 0.f;
    for (int cin = 0; cin < CIN; cin++)
        acc += s2[cin] * g_wsqT[cin * COUT + t];
    g_dcoefs[b * COUT + t] = rsqrtf(acc + 1e-8f);
}

// ---------------------------------------------------------------------------
// Kernel 4: conv (shared weight, input modulated on load, output demodulated)
// CTA: 16x16 spatial tile x 64 couts.  256 threads.
// thread: 2x2 pixels x 16 couts = 64 fp32 accumulators.
// cin processed in chunks of 8 through smem.
// ---------------------------------------------------------------------------
__global__ __launch_bounds__(256, 2)
void k_conv(const float* __restrict__ x,
            const float* __restrict__ weight,
            const float* __restrict__ bias,
            const float* __restrict__ noise_const,
            const float* __restrict__ noise_strength,
            float* __restrict__ out) {
    const int sp    = blockIdx.x;            // 0..15 spatial tile
    const int cout0 = blockIdx.y * 64;       // 0..7  cout tile
    const int b     = blockIdx.z;            // batch
    const int h0 = (sp >> 2) * 16;
    const int w0 = (sp & 3) * 16;

    const int tid = threadIdx.x;
    const int pc  = tid >> 6;                // 0..3  cout sub-group
    const int pid = tid & 63;                // 0..63 pixel sub-tile
    const int py  = (pid >> 3) * 2;          // pixel row base (0..14, even)
    const int px  = (pid & 7) * 2;           // pixel col base (0..14, even)
    const int cb  = pc * 16;                 // local cout base

    __shared__ float sx[8][18][19];                   // x tile + halo (10.9 KB)
    __shared__ __align__(16) float swt[8 * 9 * 64];   // weights (18.4 KB)

    float acc[4][16];
#pragma unroll
    for (int p = 0; p < 4; p++)
#pragma unroll
        for (int c = 0; c < 16; c++) acc[p][c] = 0.f;

    for (int cin0 = 0; cin0 < CIN; cin0 += 8) {
        __syncthreads();   // previous chunk's reads done before overwrite

        // ---- load x tile (8 cins x 18x18, zero-padded), modulated by styles
#pragma unroll
        for (int l = 0; l < 11; l++) {
            const int idx = tid + l * 256;
            if (idx < 8 * 324) {
                const int cc  = idx / 324;
                const int rem = idx - cc * 324;
                const int r   = rem / 18;
                const int col = rem - r * 18;
                const int gh = h0 + r - 1;
                const int gw = w0 + col - 1;
                float v = 0.f;
                if ((unsigned)gh < 64u && (unsigned)gw < 64u)
                    v = x[(((size_t)b * CIN + cin0 + cc) * RES + gh) * RES + gw]
                        * g_styles[b * CIN + cin0 + cc];
                sx[cc][r][col] = v;
            }
        }

        // ---- load weight tile: swt[(cc*9+tap)*64 + c] = weight[cout0+c][cin0+cc][tap]
        {
            const int c = tid >> 2;          // 0..63 local cout
            const int p = tid & 3;
            const float* __restrict__ row =
                weight + ((size_t)(cout0 + c) * CIN + cin0) * 9 + p * 18;
#pragma unroll
            for (int i = 0; i < 18; i++) {
                const int j = p * 18 + i;    // j = cc*9 + tap  (0..71)
                swt[j * 64 + c] = row[i];
            }
        }
        __syncthreads();

        // ---- compute
#pragma unroll 1
        for (int cc = 0; cc < 8; cc++) {
            float xv[4][4];
#pragma unroll
            for (int r = 0; r < 4; r++)
#pragma unroll
                for (int q = 0; q < 4; q++)
                    xv[r][q] = sx[cc][py + r][px + q];

#pragma unroll
            for (int dh = 0; dh < 3; dh++)
#pragma unroll
            for (int dw = 0; dw < 3; dw++) {
                const float4* __restrict__ wp =
                    (const float4*)&swt[(cc * 9 + dh * 3 + dw) * 64 + cb];
                const float x00 = xv[dh][dw];
                const float x01 = xv[dh][dw + 1];
                const float x10 = xv[dh + 1][dw];
                const float x11 = xv[dh + 1][dw + 1];
#pragma unroll
                for (int cg = 0; cg < 4; cg++) {
                    const float4 w4 = wp[cg];
                    acc[0][cg*4+0] += x00 * w4.x; acc[0][cg*4+1] += x00 * w4.y;
                    acc[0][cg*4+2] += x00 * w4.z; acc[0][cg*4+3] += x00 * w4.w;
                    acc[1][cg*4+0] += x01 * w4.x; acc[1][cg*4+1] += x01 * w4.y;
                    acc[1][cg*4+2] += x01 * w4.z; acc[1][cg*4+3] += x01 * w4.w;
                    acc[2][cg*4+0] += x10 * w4.x; acc[2][cg*4+1] += x10 * w4.y;
                    acc[2][cg*4+2] += x10 * w4.z; acc[2][cg*4+3] += x10 * w4.w;
                    acc[3][cg*4+0] += x11 * w4.x; acc[3][cg*4+1] += x11 * w4.y;
                    acc[3][cg*4+2] += x11 * w4.z; acc[3][cg*4+3] += x11 * w4.w;
                }
            }
        }
    }

    // ---- epilogue: demodulate, noise, bias, lrelu * sqrt(2)
    const float nstr = noise_strength[0];
    float nz[4];
#pragma unroll
    for (int p = 0; p < 4; p++) {
        const int hh = h0 + py + (p >> 1);
        const int ww = w0 + px + (p & 1);
        nz[p] = noise_const[hh * RES + ww] * nstr;
    }
#pragma unroll
    for (int c = 0; c < 16; c++) {
        const int co   = cout0 + cb + c;
        const float dc = g_dcoefs[b * COUT + co];
        const float bi = bias[co];
#pragma unroll
        for (int p = 0; p < 4; p++) {
            const int hh = h0 + py + (p >> 1);
            const int ww = w0 + px + (p & 1);
            float v = acc[p][c] * dc + nz[p] + bi;
            v = (v > 0.f ? v : 0.2f * v) * 1.4142135623730951f;
            out[(((size_t)b * COUT + co) * RES + hh) * RES + ww] = v;
        }
    }
}

// ---------------------------------------------------------------------------
// launch
// ---------------------------------------------------------------------------
extern "C" void kernel_launch(void* const* d_in, const int* in_sizes, int n_in,
                              void* d_out, int out_size) {
    (void)in_sizes; (void)n_in; (void)out_size;
    const float* x              = (const float*)d_in[0];
    const float* w              = (const float*)d_in[1];
    const float* affine_w       = (const float*)d_in[2];
    const float* affine_b       = (const float*)d_in[3];
    const float* weight         = (const float*)d_in[4];
    const float* bias           = (const float*)d_in[5];
    const float* noise_const    = (const float*)d_in[6];
    const float* noise_strength = (const float*)d_in[7];
    float* out = (float*)d_out;

    k_styles<<<BB, 512>>>(w, affine_w, affine_b);
    k_wsq<<<(CIN * COUT) / 256, 256>>>(weight);
    k_dcoefs<<<BB, 512>>>();

    dim3 grid(16, COUT / 64, BB);
    k_conv<<<grid, 256>>>(x, weight, bias, noise_const, noise_strength, out);
}

// round 4
// speedup vs baseline: 1.8553x; 1.8553x over previous
#include <cuda_runtime.h>
#include <cuda_bf16.h>
#include <cstdint>

#define BB    16
#define CIN   512
#define COUT  512
#define RES   64
#define WDIM  512
#define PADW  66
#define NPIX  (PADW * PADW)

// ---------------------------------------------------------------------------
// device scratch (static globals — no allocations allowed)
// ---------------------------------------------------------------------------
__device__ float g_styles[BB * CIN];
__device__ float g_wsqT[CIN * COUT];
__device__ float g_dcoefs[BB * COUT];
// packed weights: [tap][cout][cin], bf16 hi/lo planes
__device__ __align__(1024) __nv_bfloat16 g_ah[9ull * COUT * CIN];
__device__ __align__(1024) __nv_bfloat16 g_al[9ull * COUT * CIN];
// packed modulated input: [b][padded pixel][cin], bf16 hi/lo planes
__device__ __align__(1024) __nv_bfloat16 g_xh[(size_t)BB * NPIX * CIN];
__device__ __align__(1024) __nv_bfloat16 g_xl[(size_t)BB * NPIX * CIN];

// ---------------------------------------------------------------------------
// PTX helpers (all baseline compute_103-safe: no tcgen05)
// ---------------------------------------------------------------------------
__device__ __forceinline__ uint32_t smem_u32(const void* p) {
    uint32_t a;
    asm("{ .reg .u64 t; cvta.to.shared.u64 t, %1; cvt.u32.u64 %0, t; }" : "=r"(a) : "l"(p));
    return a;
}
__device__ __forceinline__ void cpa16(uint32_t dst, const void* src) {
    asm volatile("cp.async.cg.shared.global [%0], [%1], 16;" :: "r"(dst), "l"(src));
}
#define CP_COMMIT()  asm volatile("cp.async.commit_group;" ::: "memory")
#define CP_WAIT1()   asm volatile("cp.async.wait_group 1;" ::: "memory")
#define CP_WAIT0()   asm volatile("cp.async.wait_group 0;" ::: "memory")

__device__ __forceinline__ void ldsm4(uint32_t* r, uint32_t a) {
    asm volatile("ldmatrix.sync.aligned.m8n8.x4.shared.b16 {%0,%1,%2,%3}, [%4];"
        : "=r"(r[0]), "=r"(r[1]), "=r"(r[2]), "=r"(r[3]) : "r"(a));
}
__device__ __forceinline__ void ldsm2(uint32_t* r, uint32_t a) {
    asm volatile("ldmatrix.sync.aligned.m8n8.x2.shared.b16 {%0,%1}, [%2];"
        : "=r"(r[0]), "=r"(r[1]) : "r"(a));
}
__device__ __forceinline__ void mma_bf16(float* c, const uint32_t* a, const uint32_t* b) {
    asm volatile("mma.sync.aligned.m16n8k16.row.col.f32.bf16.bf16.f32 "
        "{%0,%1,%2,%3}, {%4,%5,%6,%7}, {%8,%9}, {%0,%1,%2,%3};"
        : "+f"(c[0]), "+f"(c[1]), "+f"(c[2]), "+f"(c[3])
        : "r"(a[0]), "r"(a[1]), "r"(a[2]), "r"(a[3]), "r"(b[0]), "r"(b[1]));
}
__device__ __forceinline__ uint32_t sw128(uint32_t off) {
    return off ^ ((off >> 3) & 0x70);
}

// ---------------------------------------------------------------------------
// prep kernels
// ---------------------------------------------------------------------------
__global__ void k_styles(const float* __restrict__ w,
                         const float* __restrict__ affine_w,
                         const float* __restrict__ affine_b) {
    const int b = blockIdx.x, t = threadIdx.x;
    __shared__ float sw[WDIM];
    sw[t] = w[b * WDIM + t];
    __syncthreads();
    const float gain = 1.0f / sqrtf((float)WDIM);
    float m[3];
#pragma unroll
    for (int j0 = 0; j0 < 3; j0++) {
        const int j = j0 * CIN + t;
        const float* __restrict__ row = affine_w + (size_t)j * WDIM;
        float acc = 0.f;
        for (int k = 0; k < WDIM; k++) acc += row[k] * sw[k];
        m[j0] = acc * gain + affine_b[j];
    }
    g_styles[b * CIN + t] = m[0] * m[1] + m[2];
}

__global__ void k_wsq(const float* __restrict__ weight) {
    const int id = blockIdx.x * blockDim.x + threadIdx.x;
    const int cin = id / COUT, cout = id - cin * COUT;
    const float* __restrict__ p = weight + ((size_t)cout * CIN + cin) * 9;
    float s = 0.f;
#pragma unroll
    for (int i = 0; i < 9; i++) { float v = p[i]; s += v * v; }
    g_wsqT[cin * COUT + cout] = s;
}

__global__ void k_dcoefs() {
    const int b = blockIdx.x, t = threadIdx.x;
    __shared__ float s2[CIN];
    const float st = g_styles[b * CIN + t];
    s2[t] = st * st;
    __syncthreads();
    float acc = 0.f;
    for (int cin = 0; cin < CIN; cin++) acc += s2[cin] * g_wsqT[cin * COUT + t];
    g_dcoefs[b * COUT + t] = rsqrtf(acc + 1e-8f);
}

__global__ void k_pack_w(const float* __restrict__ weight) {
    const int co = blockIdx.x, ci = threadIdx.x;
    const float* __restrict__ wp = weight + ((size_t)co * CIN + ci) * 9;
#pragma unroll
    for (int t = 0; t < 9; t++) {
        float v = wp[t];
        __nv_bfloat16 hi = __float2bfloat16(v);
        __nv_bfloat16 lo = __float2bfloat16(v - __bfloat162float(hi));
        size_t o = ((size_t)t * COUT + co) * CIN + ci;
        g_ah[o] = hi; g_al[o] = lo;
    }
}

__global__ void k_zero_ring() {
    const int blk = blockIdx.x;
    const int b = blk / 260, r = blk - b * 260;
    const int ci = threadIdx.x;
    int ph, pw;
    if (r < 66)       { ph = 0;       pw = r; }
    else if (r < 132) { ph = 65;      pw = r - 66; }
    else if (r < 196) { ph = r - 131; pw = 0; }
    else              { ph = r - 195; pw = 65; }
    size_t o = ((size_t)b * NPIX + ph * PADW + pw) * CIN + ci;
    g_xh[o] = __float2bfloat16(0.f);
    g_xl[o] = __float2bfloat16(0.f);
}

__global__ void k_pack_x(const float* __restrict__ x) {
    const int b = blockIdx.z, h = blockIdx.y, cin0 = blockIdx.x * 32;
    const int t = threadIdx.x;
    __shared__ float tile[32][65];
    {
        const int w = t & 63, i0 = t >> 6;
#pragma unroll
        for (int j = 0; j < 8; j++) {
            const int ci = i0 * 8 + j;
            tile[ci][w] = x[(((size_t)b * CIN + cin0 + ci) * RES + h) * RES + w];
        }
    }
    __syncthreads();
    {
        const int c = t & 31, w0 = t >> 5;
        const float st = g_styles[b * CIN + cin0 + c];
        for (int w = w0; w < 64; w += 8) {
            float v = tile[c][w] * st;
            __nv_bfloat16 hi = __float2bfloat16(v);
            __nv_bfloat16 lo = __float2bfloat16(v - __bfloat162float(hi));
            size_t o = ((size_t)b * NPIX + (h + 1) * PADW + (w + 1)) * CIN + cin0 + c;
            g_xh[o] = hi; g_xl[o] = lo;
        }
    }
}

// ---------------------------------------------------------------------------
// main conv kernel: mma.sync bf16 implicit GEMM (3-combo hi/lo split)
// CTA: M=128 couts x N=128 pixels (2 rows x 64), 8 warps, warp tile 64x32
// K-loop: 9 taps x 8 cin-chunks of 64 = 72 iters, 2-stage cp.async pipeline
// ---------------------------------------------------------------------------
#define OFF_AH  0
#define OFF_AL  16384
#define OFF_BH  32768
#define OFF_BL  49152
#define STAGE   65536
#define SMEM_DYN (2 * STAGE)

extern __shared__ __align__(1024) char smem[];

__global__ void __launch_bounds__(256, 1)
k_conv(const float* __restrict__ bias,
       const float* __restrict__ noise_const,
       const float* __restrict__ noise_strength,
       float* __restrict__ out) {
    const int tid   = threadIdx.x;
    const int wid   = tid >> 5;
    const int lid   = tid & 31;
    const int ptile = blockIdx.x;            // 0..31 (128 pixels = 2 rows each)
    const int cout0 = blockIdx.y * 128;      // 0..3
    const int b     = blockIdx.z;            // batch
    const int wm    = wid >> 2;              // 0..1  (M warp)
    const int wn    = wid & 3;               // 0..3  (N warp)

    const uint32_t sb = smem_u32(smem);

    // ---- loader invariants: 256 threads = 128 rows x {hi,lo} plane
    const int rowid = tid & 127;
    const bool hi_plane = (tid < 128);
    const __nv_bfloat16* aplane = hi_plane ? g_ah : g_al;
    const __nv_bfloat16* xplane = hi_plane ? g_xh : g_xl;
    const uint32_t offA = hi_plane ? OFF_AH : OFF_AL;
    const uint32_t offB = hi_plane ? OFF_BH : OFF_BL;

    const int gp = ptile * 128 + rowid;            // global pixel for B row
    const int bh_ = gp >> 6, bw_ = gp & 63;
    const size_t pixrow = (size_t)b * NPIX + bh_ * PADW + bw_;
    const size_t arow   = (size_t)(cout0 + rowid) * CIN;

    uint32_t sw[8];
#pragma unroll
    for (int sg = 0; sg < 8; sg++) sw[sg] = sw128((uint32_t)(rowid * 128 + sg * 16));

    // ---- ldmatrix per-lane base offsets
    uint32_t aoff[4], boff[4];
#pragma unroll
    for (int mt = 0; mt < 4; mt++)
        aoff[mt] = (uint32_t)((wm * 64 + mt * 16 + (lid & 15)) << 7) + ((lid >> 4) << 4);
#pragma unroll
    for (int nt = 0; nt < 4; nt++)
        boff[nt] = (uint32_t)((wn * 32 + nt * 8 + (lid & 7)) << 7) + (((lid >> 3) & 1) << 4);

    float acc[4][4][4];
#pragma unroll
    for (int mt = 0; mt < 4; mt++)
#pragma unroll
        for (int nt = 0; nt < 4; nt++)
#pragma unroll
            for (int i = 0; i < 4; i++) acc[mt][nt][i] = 0.f;

    // ---- stage loader
    auto load_stage = [&](int it) {
        const int tap = it >> 3, cin0 = (it & 7) << 6;
        const int dh = tap / 3, dw = tap - dh * 3;
        const uint32_t stg = sb + (uint32_t)(it & 1) * STAGE;
        const char* asrc = (const char*)(aplane + ((size_t)tap * COUT * CIN + arow + cin0));
        const char* bsrc = (const char*)(xplane + ((pixrow + dh * PADW + dw) * CIN + cin0));
        const uint32_t da = stg + offA, db = stg + offB;
#pragma unroll
        for (int sg = 0; sg < 8; sg++) {
            cpa16(da + sw[sg], asrc + sg * 16);
            cpa16(db + sw[sg], bsrc + sg * 16);
        }
        CP_COMMIT();
    };

    load_stage(0);

#pragma unroll 1
    for (int it = 0; it < 72; it++) {
        if (it + 1 < 72) { load_stage(it + 1); CP_WAIT1(); }
        else             { CP_WAIT0(); }
        __syncthreads();

        const uint32_t stgA = sb + (uint32_t)(it & 1) * STAGE + OFF_AH;
        const uint32_t stgB = sb + (uint32_t)(it & 1) * STAGE + OFF_BH;

#pragma unroll
        for (int kk = 0; kk < 4; kk++) {
            uint32_t ah[4][4], al[4][4];
#pragma unroll
            for (int mt = 0; mt < 4; mt++) {
                const uint32_t ad = stgA + sw128(aoff[mt] + kk * 32);
                ldsm4(ah[mt], ad);
                ldsm4(al[mt], ad + 16384);
            }
#pragma unroll
            for (int nt = 0; nt < 4; nt++) {
                uint32_t bhf[2], blf[2];
                const uint32_t bd = stgB + sw128(boff[nt] + kk * 32);
                ldsm2(bhf, bd);
                ldsm2(blf, bd + 16384);
#pragma unroll
                for (int mt = 0; mt < 4; mt++) {
                    mma_bf16(acc[mt][nt], ah[mt], bhf);   // hi*hi
                    mma_bf16(acc[mt][nt], al[mt], bhf);   // lo*hi
                    mma_bf16(acc[mt][nt], ah[mt], blf);   // hi*lo
                }
            }
        }
        __syncthreads();
    }

    // ---- epilogue: demodulate, noise, bias, lrelu*sqrt(2), float2 stores
    const int g = lid >> 2, t2 = (lid & 3) * 2;
    const float ns = noise_strength[0];
    float nz[4][2];
    int hh[4], ww[4];
#pragma unroll
    for (int nt = 0; nt < 4; nt++) {
        const int n = ptile * 128 + wn * 32 + nt * 8 + t2;
        hh[nt] = n >> 6; ww[nt] = n & 63;
        nz[nt][0] = noise_const[hh[nt] * RES + ww[nt]] * ns;
        nz[nt][1] = noise_const[hh[nt] * RES + ww[nt] + 1] * ns;
    }
#pragma unroll
    for (int mt = 0; mt < 4; mt++) {
#pragma unroll
        for (int rr = 0; rr < 2; rr++) {
            const int co = cout0 + wm * 64 + mt * 16 + g + rr * 8;
            const float dc = g_dcoefs[b * COUT + co];
            const float bi = bias[co];
#pragma unroll
            for (int nt = 0; nt < 4; nt++) {
                float v0 = acc[mt][nt][rr * 2 + 0] * dc + nz[nt][0] + bi;
                float v1 = acc[mt][nt][rr * 2 + 1] * dc + nz[nt][1] + bi;
                v0 = (v0 > 0.f ? v0 : 0.2f * v0) * 1.4142135623730951f;
                v1 = (v1 > 0.f ? v1 : 0.2f * v1) * 1.4142135623730951f;
                float2* o = (float2*)&out[(((size_t)b * COUT + co) * RES + hh[nt]) * RES + ww[nt]];
                *o = make_float2(v0, v1);
            }
        }
    }
}

// ---------------------------------------------------------------------------
// launch
// ---------------------------------------------------------------------------
extern "C" void kernel_launch(void* const* d_in, const int* in_sizes, int n_in,
                              void* d_out, int out_size) {
    (void)in_sizes; (void)n_in; (void)out_size;
    const float* x              = (const float*)d_in[0];
    const float* w              = (const float*)d_in[1];
    const float* affine_w       = (const float*)d_in[2];
    const float* affine_b       = (const float*)d_in[3];
    const float* weight         = (const float*)d_in[4];
    const float* bias           = (const float*)d_in[5];
    const float* noise_const    = (const float*)d_in[6];
    const float* noise_strength = (const float*)d_in[7];
    float* out = (float*)d_out;

    cudaFuncSetAttribute(k_conv, cudaFuncAttributeMaxDynamicSharedMemorySize, SMEM_DYN);

    k_styles<<<BB, 512>>>(w, affine_w, affine_b);
    k_wsq<<<(CIN * COUT) / 256, 256>>>(weight);
    k_dcoefs<<<BB, 512>>>();
    k_pack_w<<<COUT, CIN>>>(weight);
    k_zero_ring<<<BB * 260, CIN>>>();
    k_pack_x<<<dim3(16, RES, BB), 256>>>(x);

    dim3 grid(32, COUT / 128, BB);
    k_conv<<<grid, 256, SMEM_DYN>>>(bias, noise_const, noise_strength, out);
}